// round 17
// baseline (speedup 1.0000x reference)
#include <cuda_runtime.h>

#define N_ATOMS 25000
#define N_EDGES 1000000
#define N_SP 119
#define N_ROWS (N_SP * N_SP)        // 14161 coeff rows
#define PAD 36                      // padded row: 36 floats = 144B, 16B-aligned
#define PAD_TOTAL (N_ROWS * PAD)    // 509796
#define CAP 128                     // payload slots per atom (Poisson(38.8): overflow P < 1e-50)

__device__ __align__(16) float g_cpad[PAD_TOTAL];
__device__ __align__(16) float4 g_pay[N_ATOMS * CAP * 2];  // per-edge payload: rad[5], dn[3]
__device__ __align__(16) float g_mom[N_ATOMS * 100];       // [atom][100] unique moments
__device__ int g_cursor[N_ATOMS];                          // slot cursor == final count

__device__ __forceinline__ float edge_r2(float x, float y, float z) {
    return __fadd_rn(__fadd_rn(__fmul_rn(x, x), __fmul_rn(y, y)), __fmul_rn(z, z));
}
#define R2_CUT 36.0f   // dr >= 6  <=>  r2 >= 36

// K0: repack coeffs into padded rows + zero cursors
__global__ void __launch_bounds__(256) prep_kernel(const float* __restrict__ coeffs) {
    int t = blockIdx.x * blockDim.x + threadIdx.x;
    if (t < PAD_TOTAL) {
        int row = t / PAD, col = t - row * PAD;
        g_cpad[t] = (col < 35) ? coeffs[row * 35 + col] : 0.0f;
    }
    if (t < N_ATOMS) g_cursor[t] = 0;
}

// K1: per-edge math + scatter of 32B payload into the atom's padded slot range.
__global__ void __launch_bounds__(256) mathscatter_kernel(
    const float* __restrict__ dr_vec,
    const int*   __restrict__ Z,
    const int*   __restrict__ nbr)
{
    int e = blockIdx.x * blockDim.x + threadIdx.x;
    if (e >= N_EDGES) return;

    float x = dr_vec[3*e + 0];
    float y = dr_vec[3*e + 1];
    float z = dr_vec[3*e + 2];
    float r2 = edge_r2(x, y, z);
    if (r2 >= R2_CUT) return;          // cutoff exactly zero beyond 6
    float dr = sqrtf(r2);

    int ai = nbr[e];
    int aj = nbr[N_EDGES + e];
    int Zi = Z[ai];
    int Zj = Z[aj];

    const float BETTA     = 1.36111111f;        // 49/36
    const float RAD_NORM  = 0.8981114f;         // (2*betta/pi)^0.75
    const float PI_OVER_6 = 0.52359877559f;
    const float INV_SQRT7 = 0.37796447301f;
    const float KB0 = expf(-1.36111111f * 1.0f);
    const float KB1 = expf(-1.36111111f * 3.0f);
    const float KB2 = expf(-1.36111111f * 5.0f);
    const float KB3 = expf(-1.36111111f * 7.0f);
    const float KB4 = expf(-1.36111111f * 9.0f);
    const float KB5 = expf(-1.36111111f * 11.0f);

    const float4* crow = (const float4*)(g_cpad + (Zi * N_SP + Zj) * PAD);
    float4 q0 = crow[0], q1 = crow[1], q2 = crow[2], q3 = crow[3];
    float4 q4 = crow[4], q5 = crow[5], q6 = crow[6], q7 = crow[7];
    float4 q8 = crow[8];

    float inv = 1.0f / (dr + 1e-5f);
    float dx = x * inv, dy = y * inv, dz = z * inv;

    float cut = 0.5f * (__cosf(dr * PI_OVER_6) + 1.0f);
    float scale = cut * INV_SQRT7;

    // Gaussian basis via recurrence: bas[b+1] = bas[b] * G * K[b]
    float G  = __expf(2.0f * BETTA * dr);
    float b0 = RAD_NORM * scale * __expf(-BETTA * r2);  // scale folded in
    float b1 = b0 * G * KB0;
    float b2 = b1 * G * KB1;
    float b3 = b2 * G * KB2;
    float b4 = b3 * G * KB3;
    float b5 = b4 * G * KB4;
    float b6 = b5 * G * KB5;

    float r0 = q0.x*b0 + q0.y*b1 + q0.z*b2 + q0.w*b3 + q1.x*b4 + q1.y*b5 + q1.z*b6;
    float r1 = q1.w*b0 + q2.x*b1 + q2.y*b2 + q2.z*b3 + q2.w*b4 + q3.x*b5 + q3.y*b6;
    float r2_ = q3.z*b0 + q3.w*b1 + q4.x*b2 + q4.y*b3 + q4.z*b4 + q4.w*b5 + q5.x*b6;
    float r3 = q5.y*b0 + q5.z*b1 + q5.w*b2 + q6.x*b3 + q6.y*b4 + q6.z*b5 + q6.w*b6;
    float r4 = q7.x*b0 + q7.y*b1 + q7.z*b2 + q7.w*b3 + q8.x*b4 + q8.y*b5 + q8.z*b6;

    int slot = atomicAdd(&g_cursor[aj], 1);
    if (slot >= CAP) return;            // unreachable guard (keeps writes in-bounds)
    int base = (aj * CAP + slot) * 2;
    g_pay[base + 0] = make_float4(r0, r1, r2_, r3);
    g_pay[base + 1] = make_float4(r4, dx, dy, dz);
}

// K2: gather only — one warp per atom; lane u (<20) owns component u for all 5
// radials; writes the 100 unique moments to g_mom[atom][100].
__global__ void __launch_bounds__(256) gather_kernel()
{
    __shared__ __align__(16) float sm[8][928];
    int warp = threadIdx.x >> 5;
    int lane = threadIdx.x & 31;
    int a = blockIdx.x * 8 + warp;      // grid = N_ATOMS/8 exactly

    float* EDG = sm[warp];                      // 32 edges * stride 21 Tu
    float4* PAY = (float4*)(sm[warp] + 672);    // raw payload staging

    int cnt = g_cursor[a];
    int uu = (lane < 20) ? lane : 0;

    float acc0 = 0.f, acc1 = 0.f, acc2 = 0.f, acc3 = 0.f, acc4 = 0.f;

    const float4* __restrict__ pbase = g_pay + a * (CAP * 2);
    for (int base = 0; base < cnt; base += 32) {
        int n = min(32, cnt - base);
        int nf4 = 2 * n;
        if (lane < nf4)      PAY[lane]      = pbase[2*base + lane];
        if (lane + 32 < nf4) PAY[lane + 32] = pbase[2*base + lane + 32];
        __syncwarp();
        if (lane < n) {
            float4 p1 = PAY[2*lane + 1];
            float dx = p1.y, dy = p1.z, dz = p1.w;
            float* T = EDG + lane * 21;
            float xx = dx*dx, xy = dx*dy, xz = dx*dz;
            float yy = dy*dy, yz = dy*dz, zz = dz*dz;
            T[0] = 1.0f; T[1] = dx; T[2] = dy; T[3] = dz;
            T[4] = xx; T[5] = xy; T[6] = xz; T[7] = yy; T[8] = yz; T[9] = zz;
            T[10] = xx*dx; T[11] = xx*dy; T[12] = xx*dz;
            T[13] = yy*dx; T[14] = xy*dz; T[15] = zz*dx;
            T[16] = yy*dy; T[17] = yy*dz; T[18] = zz*dy; T[19] = zz*dz;
        }
        __syncwarp();
        #pragma unroll 4
        for (int j = 0; j < n; j++) {
            float tu  = EDG[j*21 + uu];
            float4 p0 = PAY[2*j];
            float r4v = sm[warp][672 + 8*j + 4];
            acc0 += p0.x * tu;
            acc1 += p0.y * tu;
            acc2 += p0.z * tu;
            acc3 += p0.w * tu;
            acc4 += r4v  * tu;
        }
        __syncwarp();
    }

    if (lane < 20) {
        float* dst = g_mom + a * 100;
        dst[ 0 + lane] = acc0;
        dst[20 + lane] = acc1;
        dst[40 + lane] = acc2;
        dst[60 + lane] = acc3;
        dst[80 + lane] = acc4;
    }
}

// Moment accessors: M[r*20 + u]; u: 0=m0, 1..3=m1, 4..9=m2 unique, 10..19=m3 unique
#define M1A(r,i)     M[(r)*20 + 1 + (i)]
#define M2A(r,i,j)   M[(r)*20 + 4 + u2m[3*(i) + (j)]]
#define M3A(r,i,j,k) M[(r)*20 + 10 + u3m[9*(i) + 3*(j) + (k)]]
#define M2UQ(r,u)    M[(r)*20 + 4 + (u)]
#define M3UQ(r,u)    M[(r)*20 + 10 + (u)]

#define WR(f_, off_, W_, v_) do {                         \
    int idx_ = (f_) * N_ATOMS + a;                        \
    int ao_ = idx_ / (W_);                                \
    out[ao_ * 360 + (off_) + (idx_ - ao_ * (W_))] = (v_); \
} while (0)

// K3: contraction, one LANE per atom, everything in registers, full unroll.
__global__ void __launch_bounds__(128) contract2_kernel(float* __restrict__ out)
{
    int a = blockIdx.x * 128 + threadIdx.x;
    if (a >= N_ATOMS) return;

    float M[100];
    const float4* row = (const float4*)(g_mom + a * 100);
    #pragma unroll
    for (int g = 0; g < 25; g++) {
        float4 v = row[g];
        M[4*g+0] = v.x; M[4*g+1] = v.y; M[4*g+2] = v.z; M[4*g+3] = v.w;
    }

    // index tables (const + full unroll => folded to immediates)
    const int u2m[9]  = {0,1,2, 1,3,4, 2,4,5};
    const int u3m[27] = {0,1,2,1,3,4,2,4,5, 1,3,4,3,6,7,4,7,8, 2,4,5,4,7,8,5,8,9};
    const int T2I[15] = {0,1,1,2,2,2,3,3,3,3,4,4,4,4,4};
    const int T2J[15] = {0,0,1,0,1,2,0,1,2,3,0,1,2,3,4};
    const float W2[6]  = {1.f,2.f,2.f,1.f,2.f,1.f};
    const float W3[10] = {1.f,3.f,3.f,3.f,6.f,3.f,1.f,3.f,3.f,1.f};
    const int UPI[6] = {0,0,0,1,1,2};
    const int UPJ[6] = {0,1,2,1,2,2};
    const int BASE3[5] = {0,1,4,10,20};     // tril3 index base per leading r

    // contr_0
    #pragma unroll
    for (int r = 0; r < 5; r++) out[a*360 + r] = M[r*20];

    // contr_1 (15): sum_i m1r_i m1s_i
    #pragma unroll
    for (int p = 0; p < 15; p++) {
        int r = T2I[p], s = T2J[p];
        float v = M1A(r,0)*M1A(s,0) + M1A(r,1)*M1A(s,1) + M1A(r,2)*M1A(s,2);
        WR(p, 5, 15, v);
    }

    // contr_2 (15): weighted unique
    #pragma unroll
    for (int p = 0; p < 15; p++) {
        int r = T2I[p], s = T2J[p];
        float v = 0.f;
        #pragma unroll
        for (int u = 0; u < 6; u++) v += (W2[u] * M2UQ(r,u)) * M2UQ(s,u);
        WR(p, 20, 15, v);
    }

    // contr_3 (15): weighted unique
    #pragma unroll
    for (int p = 0; p < 15; p++) {
        int r = T2I[p], s = T2J[p];
        float v = 0.f;
        #pragma unroll
        for (int u = 0; u < 10; u++) v += (W3[u] * M3UQ(r,u)) * M3UQ(s,u);
        WR(p, 35, 15, v);
    }

    // contr_4 (35): grouped by (r,s) with transient C4[9]
    #pragma unroll
    for (int p = 0; p < 15; p++) {
        int r = T2I[p], s = T2J[p];
        float C4v[9];
        #pragma unroll
        for (int j = 0; j < 3; j++)
            #pragma unroll
            for (int k = 0; k < 3; k++)
                C4v[3*j+k] = M2A(r,0,j)*M2A(s,0,k) + M2A(r,1,j)*M2A(s,1,k)
                           + M2A(r,2,j)*M2A(s,2,k);
        #pragma unroll
        for (int t = 0; t < 5; t++) {
            if (t <= T2J[p]) {
                float v = 0.f;
                #pragma unroll
                for (int j = 0; j < 3; j++)
                    #pragma unroll
                    for (int k = 0; k < 3; k++)
                        v += C4v[3*j+k] * M2A(t,j,k);
                int q = BASE3[r] + (s*(s+1))/2 + t;
                WR(q, 50, 35, v);
            }
        }
    }

    // contr_5 (75): grouped by (r,s) with transient B[9]
    #pragma unroll
    for (int p = 0; p < 15; p++) {
        int r = T2I[p], s = T2J[p];
        float B[9];
        #pragma unroll
        for (int i = 0; i < 3; i++)
            #pragma unroll
            for (int j = 0; j < 3; j++)
                B[3*i+j] = M1A(r,i) * M1A(s,j);
        #pragma unroll
        for (int t = 0; t < 5; t++) {
            float v = 0.f;
            #pragma unroll
            for (int i = 0; i < 3; i++)
                #pragma unroll
                for (int j = 0; j < 3; j++)
                    v += B[3*i+j] * M2A(t,i,j);
            WR(p*5 + t, 85, 75, v);
        }
    }

    // contr_6 (75): grouped by (r,s) with transient C6[9]; ij-sum via unique pairs
    #pragma unroll
    for (int p = 0; p < 15; p++) {
        int r = T2I[p], s = T2J[p];
        float C6v[9];
        #pragma unroll
        for (int k = 0; k < 3; k++)
            #pragma unroll
            for (int l = 0; l < 3; l++) {
                float v = 0.f;
                #pragma unroll
                for (int u = 0; u < 6; u++)
                    v += (W2[u] * M3A(r,UPI[u],UPJ[u],k)) * M3A(s,UPI[u],UPJ[u],l);
                C6v[3*k+l] = v;
            }
        #pragma unroll
        for (int t = 0; t < 5; t++) {
            float v = 0.f;
            #pragma unroll
            for (int k = 0; k < 3; k++)
                #pragma unroll
                for (int l = 0; l < 3; l++)
                    v += C6v[3*k+l] * M2A(t,k,l);
            WR(p*5 + t, 160, 75, v);
        }
    }

    // contr_7 (125): grouped by (r,s) over ALL 25 pairs with transient E7[3]
    #pragma unroll
    for (int r = 0; r < 5; r++) {
        #pragma unroll
        for (int s = 0; s < 5; s++) {
            float E7v[3];
            #pragma unroll
            for (int k = 0; k < 3; k++) {
                float v = 0.f;
                #pragma unroll
                for (int u = 0; u < 6; u++)
                    v += (W2[u] * M3A(r,UPI[u],UPJ[u],k)) * M2A(s,UPI[u],UPJ[u]);
                E7v[k] = v;
            }
            #pragma unroll
            for (int t = 0; t < 5; t++) {
                float v = E7v[0]*M1A(t,0) + E7v[1]*M1A(t,1) + E7v[2]*M1A(t,2);
                WR(r*25 + s*5 + t, 235, 125, v);
            }
        }
    }
}

extern "C" void kernel_launch(void* const* d_in, const int* in_sizes, int n_in,
                              void* d_out, int out_size)
{
    const float* dr_vec = (const float*)d_in[0];
    const int*   Z      = (const int*)d_in[1];
    const int*   nbr    = (const int*)d_in[2];
    const float* coeffs = (const float*)d_in[3];
    float* out = (float*)d_out;

    (void)in_sizes; (void)n_in; (void)out_size;

    prep_kernel<<<(PAD_TOTAL + 255) / 256, 256>>>(coeffs);
    mathscatter_kernel<<<(N_EDGES + 255) / 256, 256>>>(dr_vec, Z, nbr);
    gather_kernel<<<N_ATOMS / 8, 256>>>();
    contract2_kernel<<<(N_ATOMS + 127) / 128, 128>>>(out);
}